// round 2
// baseline (speedup 1.0000x reference)
#include <cuda_runtime.h>

#define B_ 8
#define N_ 2048
#define F_ 256
#define OUT_OFF (B_ * N_ * F_)

// Scratch (device globals: no allocations allowed in kernel_launch)
__device__ float g_Wh[B_ * N_ * F_];   // 16 MB
__device__ float g_Wh1[B_ * N_];
__device__ float g_Wh2[B_ * N_];

// ---------------------------------------------------------------------------
// Kernel 1: Wh = h @ W     (M = B*N = 16384, K = 256, Ncols = 256)
// 64x64 tile, TK=16, 256 threads, 4x4 per thread, fp32.
// ---------------------------------------------------------------------------
__global__ __launch_bounds__(256) void wh_gemm(const float* __restrict__ h,
                                               const float* __restrict__ W) {
    __shared__ float As[16][68];   // transposed A tile (k-major)
    __shared__ float Bs[16][68];
    const int t = threadIdx.x;
    const int tx = t & 15, ty = t >> 4;
    const int rowBase = blockIdx.y * 64;
    const int colBase = blockIdx.x * 64;
    const int la_r = t >> 2;            // 0..63
    const int la_c = (t & 3) * 4;       // 0,4,8,12
    const int lb_r = t >> 4;            // 0..15
    const int lb_c = (t & 15) * 4;      // 0..60
    float acc[4][4] = {};

    for (int k0 = 0; k0 < F_; k0 += 16) {
        float4 av = *(const float4*)&h[(size_t)(rowBase + la_r) * F_ + k0 + la_c];
        float4 bv = *(const float4*)&W[(size_t)(k0 + lb_r) * F_ + colBase + lb_c];
        __syncthreads();
        As[la_c + 0][la_r] = av.x;
        As[la_c + 1][la_r] = av.y;
        As[la_c + 2][la_r] = av.z;
        As[la_c + 3][la_r] = av.w;
        *(float4*)&Bs[lb_r][lb_c] = bv;
        __syncthreads();
#pragma unroll
        for (int k = 0; k < 16; ++k) {
            float4 aq = *(const float4*)&As[k][ty * 4];
            float4 bq = *(const float4*)&Bs[k][tx * 4];
            float a4[4] = {aq.x, aq.y, aq.z, aq.w};
            float b4[4] = {bq.x, bq.y, bq.z, bq.w};
#pragma unroll
            for (int i = 0; i < 4; ++i)
#pragma unroll
                for (int j = 0; j < 4; ++j)
                    acc[i][j] = fmaf(a4[i], b4[j], acc[i][j]);
        }
    }
#pragma unroll
    for (int i = 0; i < 4; ++i) {
        const size_t r = (size_t)(rowBase + ty * 4 + i);
#pragma unroll
        for (int j = 0; j < 4; ++j)
            g_Wh[r * F_ + colBase + tx * 4 + j] = acc[i][j];
    }
}

// ---------------------------------------------------------------------------
// Kernel 2: Wh1 = Wh @ a[:F], Wh2 = Wh @ a[F:]   — one warp per row
// ---------------------------------------------------------------------------
__global__ __launch_bounds__(256) void attvec(const float* __restrict__ a) {
    const int warp = threadIdx.x >> 5, lane = threadIdx.x & 31;
    const int row = blockIdx.x * 8 + warp;
    const float* wh = g_Wh + (size_t)row * F_;
    float s1 = 0.f, s2 = 0.f;
#pragma unroll
    for (int i = 0; i < 8; ++i) {
        const int c = lane + i * 32;
        const float v = wh[c];
        s1 = fmaf(v, a[c], s1);
        s2 = fmaf(v, a[F_ + c], s2);
    }
#pragma unroll
    for (int o = 16; o; o >>= 1) {
        s1 += __shfl_xor_sync(0xffffffffu, s1, o);
        s2 += __shfl_xor_sync(0xffffffffu, s2, o);
    }
    if (lane == 0) {
        g_Wh1[row] = s1;
        g_Wh2[row] = s2;
    }
}

// ---------------------------------------------------------------------------
// Kernel 3: masked leaky-relu + row softmax -> attention (written to d_out)
// One block per (b,i) row, 256 threads, 8 values per thread held in registers.
// ---------------------------------------------------------------------------
__global__ __launch_bounds__(256) void softmax_k(const int* __restrict__ adj,
                                                 float* __restrict__ att) {
    __shared__ float red[8];
    const int row = blockIdx.x;       // b*N + i
    const int b = row >> 11;
    const int t = threadIdx.x;
    const int* __restrict__ arow = adj + (size_t)row * N_;
    const float wh1 = g_Wh1[row];
    const float* __restrict__ wh2 = g_Wh2 + (size_t)b * N_;

    float v[8];
    float lmax = -3.0e38f;
#pragma unroll
    for (int i = 0; i < 8; ++i) {
        const int j = t + i * 256;
        const float x = wh1 + wh2[j];
        const float e = x > 0.f ? x : 0.2f * x;          // leaky_relu BEFORE mask
        const float s = arow[j] > 0 ? e : -9.0e15f;
        v[i] = s;
        lmax = fmaxf(lmax, s);
    }
#pragma unroll
    for (int o = 16; o; o >>= 1) lmax = fmaxf(lmax, __shfl_xor_sync(0xffffffffu, lmax, o));
    if ((t & 31) == 0) red[t >> 5] = lmax;
    __syncthreads();
    float m = red[0];
#pragma unroll
    for (int i = 1; i < 8; ++i) m = fmaxf(m, red[i]);
    __syncthreads();   // red reused below

    float lsum = 0.f;
#pragma unroll
    for (int i = 0; i < 8; ++i) {
        const float p = __expf(v[i] - m);
        v[i] = p;
        lsum += p;
    }
#pragma unroll
    for (int o = 16; o; o >>= 1) lsum += __shfl_xor_sync(0xffffffffu, lsum, o);
    if ((t & 31) == 0) red[t >> 5] = lsum;
    __syncthreads();
    float s = 0.f;
#pragma unroll
    for (int i = 0; i < 8; ++i) s += red[i];
    const float inv = 1.0f / s;

    float* __restrict__ orow = att + (size_t)row * N_;
#pragma unroll
    for (int i = 0; i < 8; ++i) orow[t + i * 256] = v[i] * inv;
}

// ---------------------------------------------------------------------------
// Kernel 4: h_prime = attention @ Wh ; out = h + elu(h_prime)
// Per batch: [2048 x 2048] @ [2048 x 256]. 64x64 tile, TK=16, 4x4/thread.
// ---------------------------------------------------------------------------
__global__ __launch_bounds__(256) void hprime_gemm(const float* __restrict__ att,
                                                   const float* __restrict__ h,
                                                   float* __restrict__ out) {
    __shared__ float As[16][68];
    __shared__ float Bs[16][68];
    const int t = threadIdx.x;
    const int tx = t & 15, ty = t >> 4;
    const int b = blockIdx.z;
    const int rowBase = blockIdx.y * 64;
    const int colBase = blockIdx.x * 64;
    const float* __restrict__ A = att + (size_t)b * N_ * N_;
    const float* __restrict__ Bm = g_Wh + (size_t)b * N_ * F_;
    const int la_r = t >> 2;
    const int la_c = (t & 3) * 4;
    const int lb_r = t >> 4;
    const int lb_c = (t & 15) * 4;
    float acc[4][4] = {};

    for (int k0 = 0; k0 < N_; k0 += 16) {
        float4 av = *(const float4*)&A[(size_t)(rowBase + la_r) * N_ + k0 + la_c];
        float4 bv = *(const float4*)&Bm[(size_t)(k0 + lb_r) * F_ + colBase + lb_c];
        __syncthreads();
        As[la_c + 0][la_r] = av.x;
        As[la_c + 1][la_r] = av.y;
        As[la_c + 2][la_r] = av.z;
        As[la_c + 3][la_r] = av.w;
        *(float4*)&Bs[lb_r][lb_c] = bv;
        __syncthreads();
#pragma unroll
        for (int k = 0; k < 16; ++k) {
            float4 aq = *(const float4*)&As[k][ty * 4];
            float4 bq = *(const float4*)&Bs[k][tx * 4];
            float a4[4] = {aq.x, aq.y, aq.z, aq.w};
            float b4[4] = {bq.x, bq.y, bq.z, bq.w};
#pragma unroll
            for (int i = 0; i < 4; ++i)
#pragma unroll
                for (int j = 0; j < 4; ++j)
                    acc[i][j] = fmaf(a4[i], b4[j], acc[i][j]);
        }
    }
#pragma unroll
    for (int i = 0; i < 4; ++i) {
        const size_t ridx = ((size_t)b * N_ + rowBase + ty * 4 + i) * F_;
#pragma unroll
        for (int j = 0; j < 4; ++j) {
            const size_t idx = ridx + colBase + tx * 4 + j;
            const float hp = acc[i][j];
            const float e = hp > 0.f ? hp : expm1f(hp);   // elu(alpha=1)
            out[idx] = h[idx] + e;
        }
    }
}

// ---------------------------------------------------------------------------
extern "C" void kernel_launch(void* const* d_in, const int* in_sizes, int n_in,
                              void* d_out, int out_size) {
    const float* h   = (const float*)d_in[0];
    const int*   adj = (const int*)  d_in[1];
    const float* W   = (const float*)d_in[2];
    const float* a   = (const float*)d_in[3];
    float* out = (float*)d_out;
    float* att = out + OUT_OFF;   // attention region of the tuple output

    wh_gemm<<<dim3(F_ / 64, (B_ * N_) / 64), 256>>>(h, W);
    attvec<<<(B_ * N_) / 8, 256>>>(a);
    softmax_k<<<B_ * N_, 256>>>(adj, att);
    hprime_gemm<<<dim3(F_ / 64, N_ / 64, B_), 256>>>(att, h, out);
}

// round 4
// speedup vs baseline: 2.1239x; 2.1239x over previous
#include <cuda_runtime.h>
#include <cstdint>

#define B_ 8
#define N_ 2048
#define F_ 256
#define OUT_OFF (B_ * N_ * F_)

// Scratch (device globals: no allocations allowed in kernel_launch)
__device__ float g_Wh[B_ * N_ * F_];   // 16 MB
__device__ float g_Wh1[B_ * N_];
__device__ float g_Wh2[B_ * N_];

__device__ __forceinline__ uint32_t f2tf32(float x) {
    uint32_t r;
    asm("cvt.rna.tf32.f32 %0, %1;" : "=r"(r) : "f"(x));
    return r;
}

// ---------------------------------------------------------------------------
// Kernel 1: Wh = h @ W     (M = B*N = 16384, K = 256, Ncols = 256)  fp32
// ---------------------------------------------------------------------------
__global__ __launch_bounds__(256) void wh_gemm(const float* __restrict__ h,
                                               const float* __restrict__ W) {
    __shared__ float As[16][68];
    __shared__ float Bs[16][68];
    const int t = threadIdx.x;
    const int tx = t & 15, ty = t >> 4;
    const int rowBase = blockIdx.y * 64;
    const int colBase = blockIdx.x * 64;
    const int la_r = t >> 2;
    const int la_c = (t & 3) * 4;
    const int lb_r = t >> 4;
    const int lb_c = (t & 15) * 4;
    float acc[4][4] = {};

    for (int k0 = 0; k0 < F_; k0 += 16) {
        float4 av = *(const float4*)&h[(size_t)(rowBase + la_r) * F_ + k0 + la_c];
        float4 bv = *(const float4*)&W[(size_t)(k0 + lb_r) * F_ + colBase + lb_c];
        __syncthreads();
        As[la_c + 0][la_r] = av.x;
        As[la_c + 1][la_r] = av.y;
        As[la_c + 2][la_r] = av.z;
        As[la_c + 3][la_r] = av.w;
        *(float4*)&Bs[lb_r][lb_c] = bv;
        __syncthreads();
#pragma unroll
        for (int k = 0; k < 16; ++k) {
            float4 aq = *(const float4*)&As[k][ty * 4];
            float4 bq = *(const float4*)&Bs[k][tx * 4];
            float a4[4] = {aq.x, aq.y, aq.z, aq.w};
            float b4[4] = {bq.x, bq.y, bq.z, bq.w};
#pragma unroll
            for (int i = 0; i < 4; ++i)
#pragma unroll
                for (int j = 0; j < 4; ++j)
                    acc[i][j] = fmaf(a4[i], b4[j], acc[i][j]);
        }
    }
#pragma unroll
    for (int i = 0; i < 4; ++i) {
        const size_t r = (size_t)(rowBase + ty * 4 + i);
#pragma unroll
        for (int j = 0; j < 4; ++j)
            g_Wh[r * F_ + colBase + tx * 4 + j] = acc[i][j];
    }
}

// ---------------------------------------------------------------------------
// Kernel 2: Wh1 = Wh @ a[:F], Wh2 = Wh @ a[F:]   — one warp per row
// ---------------------------------------------------------------------------
__global__ __launch_bounds__(256) void attvec(const float* __restrict__ a) {
    const int warp = threadIdx.x >> 5, lane = threadIdx.x & 31;
    const int row = blockIdx.x * 8 + warp;
    const float* wh = g_Wh + (size_t)row * F_;
    float s1 = 0.f, s2 = 0.f;
#pragma unroll
    for (int i = 0; i < 8; ++i) {
        const int c = lane + i * 32;
        const float v = wh[c];
        s1 = fmaf(v, a[c], s1);
        s2 = fmaf(v, a[F_ + c], s2);
    }
#pragma unroll
    for (int o = 16; o; o >>= 1) {
        s1 += __shfl_xor_sync(0xffffffffu, s1, o);
        s2 += __shfl_xor_sync(0xffffffffu, s2, o);
    }
    if (lane == 0) {
        g_Wh1[row] = s1;
        g_Wh2[row] = s2;
    }
}

// ---------------------------------------------------------------------------
// Kernel 3: masked leaky-relu + row softmax -> attention (written to d_out)
// ---------------------------------------------------------------------------
__global__ __launch_bounds__(256) void softmax_k(const int* __restrict__ adj,
                                                 float* __restrict__ att) {
    __shared__ float red[8];
    const int row = blockIdx.x;
    const int b = row >> 11;
    const int t = threadIdx.x;
    const int* __restrict__ arow = adj + (size_t)row * N_;
    const float wh1 = g_Wh1[row];
    const float* __restrict__ wh2 = g_Wh2 + (size_t)b * N_;

    float v[8];
    float lmax = -3.0e38f;
#pragma unroll
    for (int i = 0; i < 8; ++i) {
        const int j = t + i * 256;
        const float x = wh1 + wh2[j];
        const float e = x > 0.f ? x : 0.2f * x;
        const float s = arow[j] > 0 ? e : -9.0e15f;
        v[i] = s;
        lmax = fmaxf(lmax, s);
    }
#pragma unroll
    for (int o = 16; o; o >>= 1) lmax = fmaxf(lmax, __shfl_xor_sync(0xffffffffu, lmax, o));
    if ((t & 31) == 0) red[t >> 5] = lmax;
    __syncthreads();
    float m = red[0];
#pragma unroll
    for (int i = 1; i < 8; ++i) m = fmaxf(m, red[i]);
    __syncthreads();

    float lsum = 0.f;
#pragma unroll
    for (int i = 0; i < 8; ++i) {
        const float p = __expf(v[i] - m);
        v[i] = p;
        lsum += p;
    }
#pragma unroll
    for (int o = 16; o; o >>= 1) lsum += __shfl_xor_sync(0xffffffffu, lsum, o);
    if ((t & 31) == 0) red[t >> 5] = lsum;
    __syncthreads();
    float s = 0.f;
#pragma unroll
    for (int i = 0; i < 8; ++i) s += red[i];
    const float inv = 1.0f / s;

    float* __restrict__ orow = att + (size_t)row * N_;
#pragma unroll
    for (int i = 0; i < 8; ++i) orow[t + i * 256] = v[i] * inv;
}

// ---------------------------------------------------------------------------
// Kernel 4: h_prime = attention @ Wh via mma.sync m16n8k8 tf32
// CTA 128x128, BK=16, 8 warps (2x4), warp tile 64x32 (4x4 m16n8 subtiles).
// Epilogue: out = h + elu(h_prime)
// ---------------------------------------------------------------------------
__global__ __launch_bounds__(256) void hprime_mma(const float* __restrict__ att,
                                                  const float* __restrict__ h,
                                                  float* __restrict__ out) {
    __shared__ uint32_t As[2][128][20];   // [buf][row][k] stride 20: conflict-free frags
    __shared__ uint32_t Bs[2][16][136];   // [buf][k][col] stride 136: conflict-free frags
    const int t = threadIdx.x;
    const int wid = t >> 5, lane = t & 31;
    const int wr = wid >> 2, wc = wid & 3;          // warp row (0..1), warp col (0..3)
    const int g = lane >> 2, q = lane & 3;          // quad layout
    const int b = blockIdx.z;
    const int rowBase = blockIdx.y * 128;
    const int colBase = blockIdx.x * 128;
    const float* __restrict__ A = att + (size_t)b * N_ * N_;
    const float* __restrict__ Bm = g_Wh + (size_t)b * N_ * F_;

    // gmem staging indices (2 float4 each for A and B per thread)
    const int ia0 = t, ia1 = t + 256;               // A: row=idx>>2, k=(idx&3)*4
    const int ib0 = t, ib1 = t + 256;               // B: k=idx>>5, col=(idx&31)*4

    float acc[4][4][4] = {};
    float4 ra[2], rb[2];

    // prologue: load tile 0
    ra[0] = *(const float4*)&A[(size_t)(rowBase + (ia0 >> 2)) * N_ + ((ia0 & 3) * 4)];
    ra[1] = *(const float4*)&A[(size_t)(rowBase + (ia1 >> 2)) * N_ + ((ia1 & 3) * 4)];
    rb[0] = *(const float4*)&Bm[(size_t)(ib0 >> 5) * F_ + colBase + (ib0 & 31) * 4];
    rb[1] = *(const float4*)&Bm[(size_t)(ib1 >> 5) * F_ + colBase + (ib1 & 31) * 4];
    {
        uint4 va0 = {f2tf32(ra[0].x), f2tf32(ra[0].y), f2tf32(ra[0].z), f2tf32(ra[0].w)};
        uint4 va1 = {f2tf32(ra[1].x), f2tf32(ra[1].y), f2tf32(ra[1].z), f2tf32(ra[1].w)};
        *(uint4*)&As[0][ia0 >> 2][(ia0 & 3) * 4] = va0;
        *(uint4*)&As[0][ia1 >> 2][(ia1 & 3) * 4] = va1;
        uint4 vb0 = {f2tf32(rb[0].x), f2tf32(rb[0].y), f2tf32(rb[0].z), f2tf32(rb[0].w)};
        uint4 vb1 = {f2tf32(rb[1].x), f2tf32(rb[1].y), f2tf32(rb[1].z), f2tf32(rb[1].w)};
        *(uint4*)&Bs[0][ib0 >> 5][(ib0 & 31) * 4] = vb0;
        *(uint4*)&Bs[0][ib1 >> 5][(ib1 & 31) * 4] = vb1;
    }
    __syncthreads();

    const int KTILES = N_ / 16;   // 128
    for (int kt = 0; kt < KTILES; ++kt) {
        const int buf = kt & 1;
        if (kt + 1 < KTILES) {
            const int k0 = (kt + 1) * 16;
            ra[0] = *(const float4*)&A[(size_t)(rowBase + (ia0 >> 2)) * N_ + k0 + (ia0 & 3) * 4];
            ra[1] = *(const float4*)&A[(size_t)(rowBase + (ia1 >> 2)) * N_ + k0 + (ia1 & 3) * 4];
            rb[0] = *(const float4*)&Bm[(size_t)(k0 + (ib0 >> 5)) * F_ + colBase + (ib0 & 31) * 4];
            rb[1] = *(const float4*)&Bm[(size_t)(k0 + (ib1 >> 5)) * F_ + colBase + (ib1 & 31) * 4];
        }

#pragma unroll
        for (int s = 0; s < 2; ++s) {
            uint32_t af[4][4], bf[4][2];
#pragma unroll
            for (int mi = 0; mi < 4; ++mi) {
                const int r0 = wr * 64 + mi * 16;
                af[mi][0] = As[buf][r0 + g][s * 8 + q];
                af[mi][1] = As[buf][r0 + g + 8][s * 8 + q];
                af[mi][2] = As[buf][r0 + g][s * 8 + q + 4];
                af[mi][3] = As[buf][r0 + g + 8][s * 8 + q + 4];
            }
#pragma unroll
            for (int ni = 0; ni < 4; ++ni) {
                const int c0 = wc * 32 + ni * 8 + g;
                bf[ni][0] = Bs[buf][s * 8 + q][c0];
                bf[ni][1] = Bs[buf][s * 8 + q + 4][c0];
            }
#pragma unroll
            for (int mi = 0; mi < 4; ++mi)
#pragma unroll
                for (int ni = 0; ni < 4; ++ni) {
                    asm volatile(
                        "mma.sync.aligned.m16n8k8.row.col.f32.tf32.tf32.f32 "
                        "{%0,%1,%2,%3}, {%4,%5,%6,%7}, {%8,%9}, {%0,%1,%2,%3};"
                        : "+f"(acc[mi][ni][0]), "+f"(acc[mi][ni][1]),
                          "+f"(acc[mi][ni][2]), "+f"(acc[mi][ni][3])
                        : "r"(af[mi][0]), "r"(af[mi][1]), "r"(af[mi][2]), "r"(af[mi][3]),
                          "r"(bf[ni][0]), "r"(bf[ni][1]));
                }
        }

        if (kt + 1 < KTILES) {
            const int nb = buf ^ 1;
            uint4 va0 = {f2tf32(ra[0].x), f2tf32(ra[0].y), f2tf32(ra[0].z), f2tf32(ra[0].w)};
            uint4 va1 = {f2tf32(ra[1].x), f2tf32(ra[1].y), f2tf32(ra[1].z), f2tf32(ra[1].w)};
            *(uint4*)&As[nb][ia0 >> 2][(ia0 & 3) * 4] = va0;
            *(uint4*)&As[nb][ia1 >> 2][(ia1 & 3) * 4] = va1;
            uint4 vb0 = {f2tf32(rb[0].x), f2tf32(rb[0].y), f2tf32(rb[0].z), f2tf32(rb[0].w)};
            uint4 vb1 = {f2tf32(rb[1].x), f2tf32(rb[1].y), f2tf32(rb[1].z), f2tf32(rb[1].w)};
            *(uint4*)&Bs[nb][ib0 >> 5][(ib0 & 31) * 4] = vb0;
            *(uint4*)&Bs[nb][ib1 >> 5][(ib1 & 31) * 4] = vb1;
        }
        __syncthreads();
    }

    // epilogue: out = h + elu(h_prime), float2 stores (cols 2q, 2q+1 contiguous)
#pragma unroll
    for (int mi = 0; mi < 4; ++mi) {
        const int row0 = rowBase + wr * 64 + mi * 16 + g;
#pragma unroll
        for (int ni = 0; ni < 4; ++ni) {
            const int col = colBase + wc * 32 + ni * 8 + 2 * q;
            {
                const size_t i0 = ((size_t)b * N_ + row0) * F_ + col;
                const float h0 = acc[mi][ni][0], h1 = acc[mi][ni][1];
                float2 r;
                r.x = h[i0]     + (h0 > 0.f ? h0 : expm1f(h0));
                r.y = h[i0 + 1] + (h1 > 0.f ? h1 : expm1f(h1));
                *(float2*)&out[i0] = r;
            }
            {
                const size_t i2 = ((size_t)b * N_ + row0 + 8) * F_ + col;
                const float h2 = acc[mi][ni][2], h3 = acc[mi][ni][3];
                float2 r;
                r.x = h[i2]     + (h2 > 0.f ? h2 : expm1f(h2));
                r.y = h[i2 + 1] + (h3 > 0.f ? h3 : expm1f(h3));
                *(float2*)&out[i2] = r;
            }
        }
    }
}

// ---------------------------------------------------------------------------
extern "C" void kernel_launch(void* const* d_in, const int* in_sizes, int n_in,
                              void* d_out, int out_size) {
    const float* h   = (const float*)d_in[0];
    const int*   adj = (const int*)  d_in[1];
    const float* W   = (const float*)d_in[2];
    const float* a   = (const float*)d_in[3];
    float* out = (float*)d_out;
    float* att = out + OUT_OFF;

    wh_gemm<<<dim3(F_ / 64, (B_ * N_) / 64), 256>>>(h, W);
    attvec<<<(B_ * N_) / 8, 256>>>(a);
    softmax_k<<<B_ * N_, 256>>>(adj, att);
    hprime_mma<<<dim3(F_ / 128, N_ / 128, B_), 256>>>(att, h, out);
}

// round 5
// speedup vs baseline: 2.7057x; 1.2739x over previous
#include <cuda_runtime.h>
#include <cstdint>

#define B_ 8
#define N_ 2048
#define F_ 256
#define OUT_OFF (B_ * N_ * F_)

// Scratch (device globals: no allocations allowed anywhere)
__device__ float g_Wh[B_ * N_ * F_];   // 16 MB
__device__ float g_Wh1[B_ * N_];
__device__ float g_Wh2[B_ * N_];
__device__ float g_wa[2 * F_];         // W@a1, W@a2

// ---------------------------------------------------------------------------
// cp.async helpers
// ---------------------------------------------------------------------------
__device__ __forceinline__ void cpa16(uint32_t s, const float* g) {
    asm volatile("cp.async.cg.shared.global [%0], [%1], 16;" :: "r"(s), "l"(g));
}
__device__ __forceinline__ void cp_commit() { asm volatile("cp.async.commit_group;"); }
__device__ __forceinline__ void cp_wait2()  { asm volatile("cp.async.wait_group 2;"); }

// ---------------------------------------------------------------------------
// Unified tf32 MMA GEMM: C[128x128] tiles, BK=16, 8 warps (2x4), warp 64x32.
// A row-major [rows x KDIM] (lda), B row-major K-major [KDIM x F_] (ldb=F_).
// 4-stage cp.async pipeline, raw fp32 bits into mma.tf32 (HW truncation).
// DO_ELU: out = hres + elu(acc) ; else plain store.
// ---------------------------------------------------------------------------
#define STAGES 4
#define AW (128 * 20)          // A stage words (row stride 20: conflict-free frags)
#define BW (16 * 136)          // B stage words (k stride 136: conflict-free frags)
#define STW (AW + BW)
#define SMEM_BYTES (STAGES * STW * 4)

template <int KDIM, bool DO_ELU>
__global__ __launch_bounds__(256) void mma_gemm(
    const float* __restrict__ A, const int lda, const long sA,
    const float* __restrict__ Bm, const long sB,
    const float* __restrict__ hres, float* __restrict__ out, const long sO) {
    constexpr int KT = KDIM / 16;
    extern __shared__ uint32_t sm[];
    const int t = threadIdx.x, wid = t >> 5, lane = t & 31;
    const int wr = wid >> 2, wc = wid & 3, g = lane >> 2, q = lane & 3;
    const int z = blockIdx.z;
    const int rowBase = blockIdx.y * 128;
    const int colBase = blockIdx.x * 128;
    const float* __restrict__ Ab = A + (long)z * sA;
    const float* __restrict__ Bb = Bm + (long)z * sB;

    // staging indices: 2 x 16B for A, 2 x 16B for B per thread per stage
    const int ar0 = t >> 2, ak = (t & 3) * 4;       // A row 0..63 (+64), k-chunk
    const int bk0 = t >> 5, bc = (t & 31) * 4;      // B k 0..7 (+8), col-chunk
    const float* gA0 = Ab + (long)(rowBase + ar0) * lda + ak;
    const float* gA1 = gA0 + 64l * lda;
    const float* gB0 = Bb + (long)bk0 * F_ + colBase + bc;
    const float* gB1 = gB0 + 8l * F_;
    const uint32_t smb = (uint32_t)__cvta_generic_to_shared(sm);
    const uint32_t sA0 = smb + (ar0 * 20 + ak) * 4u;
    const uint32_t sA1 = sA0 + 64 * 20 * 4u;
    const uint32_t sB0 = smb + (AW + bk0 * 136 + bc) * 4u;
    const uint32_t sB1 = sB0 + 8 * 136 * 4u;

    // prologue: stages 0..STAGES-2
#pragma unroll
    for (int s = 0; s < STAGES - 1; ++s) {
        if (s < KT) {
            const uint32_t so = s * STW * 4u;
            const long ko = (long)s * 16;
            cpa16(sA0 + so, gA0 + ko);
            cpa16(sA1 + so, gA1 + ko);
            cpa16(sB0 + so, gB0 + ko * F_);
            cpa16(sB1 + so, gB1 + ko * F_);
        }
        cp_commit();
    }

    float acc[4][4][4] = {};
    for (int kt = 0; kt < KT; ++kt) {
        cp_wait2();
        __syncthreads();
        {   // issue tile kt+3 into buf (kt-1)&3 (free: all warps passed iter kt-1)
            const int tl = kt + (STAGES - 1);
            if (tl < KT) {
                const uint32_t so = (tl & (STAGES - 1)) * STW * 4u;
                const long ko = (long)tl * 16;
                cpa16(sA0 + so, gA0 + ko);
                cpa16(sA1 + so, gA1 + ko);
                cpa16(sB0 + so, gB0 + ko * F_);
                cpa16(sB1 + so, gB1 + ko * F_);
            }
            cp_commit();
        }
        const uint32_t* __restrict__ Asb = sm + (kt & (STAGES - 1)) * STW;
        const uint32_t* __restrict__ Bsb = Asb + AW;
#pragma unroll
        for (int s = 0; s < 2; ++s) {
            uint32_t af[4][4], bf[4][2];
#pragma unroll
            for (int mi = 0; mi < 4; ++mi) {
                const int r0 = (wr * 64 + mi * 16 + g) * 20;
                af[mi][0] = Asb[r0 + s * 8 + q];
                af[mi][1] = Asb[r0 + 160 + s * 8 + q];
                af[mi][2] = Asb[r0 + s * 8 + q + 4];
                af[mi][3] = Asb[r0 + 160 + s * 8 + q + 4];
            }
#pragma unroll
            for (int ni = 0; ni < 4; ++ni) {
                const int c0 = wc * 32 + ni * 8 + g;
                bf[ni][0] = Bsb[(s * 8 + q) * 136 + c0];
                bf[ni][1] = Bsb[(s * 8 + q + 4) * 136 + c0];
            }
#pragma unroll
            for (int mi = 0; mi < 4; ++mi)
#pragma unroll
                for (int ni = 0; ni < 4; ++ni) {
                    asm volatile(
                        "mma.sync.aligned.m16n8k8.row.col.f32.tf32.tf32.f32 "
                        "{%0,%1,%2,%3}, {%4,%5,%6,%7}, {%8,%9}, {%0,%1,%2,%3};"
                        : "+f"(acc[mi][ni][0]), "+f"(acc[mi][ni][1]),
                          "+f"(acc[mi][ni][2]), "+f"(acc[mi][ni][3])
                        : "r"(af[mi][0]), "r"(af[mi][1]), "r"(af[mi][2]), "r"(af[mi][3]),
                          "r"(bf[ni][0]), "r"(bf[ni][1]));
                }
        }
    }

    // epilogue
    const long ob = (long)z * sO;
#pragma unroll
    for (int mi = 0; mi < 4; ++mi) {
        const int r0 = rowBase + wr * 64 + mi * 16 + g;
#pragma unroll
        for (int ni = 0; ni < 4; ++ni) {
            const int col = colBase + wc * 32 + ni * 8 + 2 * q;
            const long i0 = ob + (long)r0 * F_ + col;
            const long i2 = i0 + 8l * F_;
            if (DO_ELU) {
                const float h0 = acc[mi][ni][0], h1 = acc[mi][ni][1];
                const float h2 = acc[mi][ni][2], h3 = acc[mi][ni][3];
                float2 r01, r23;
                r01.x = hres[i0]     + (h0 > 0.f ? h0 : expm1f(h0));
                r01.y = hres[i0 + 1] + (h1 > 0.f ? h1 : expm1f(h1));
                r23.x = hres[i2]     + (h2 > 0.f ? h2 : expm1f(h2));
                r23.y = hres[i2 + 1] + (h3 > 0.f ? h3 : expm1f(h3));
                *(float2*)&out[i0] = r01;
                *(float2*)&out[i2] = r23;
            } else {
                float2 r01 = {acc[mi][ni][0], acc[mi][ni][1]};
                float2 r23 = {acc[mi][ni][2], acc[mi][ni][3]};
                *(float2*)&out[i0] = r01;
                *(float2*)&out[i2] = r23;
            }
        }
    }
}

// ---------------------------------------------------------------------------
// wa = W @ a halves (fp32, exact path for attention logits). One warp per f.
// ---------------------------------------------------------------------------
__global__ __launch_bounds__(256) void wa_k(const float* __restrict__ W,
                                            const float* __restrict__ a) {
    const int warp = threadIdx.x >> 5, lane = threadIdx.x & 31;
    const int f = blockIdx.x * 8 + warp;
    const float* wrow = W + (size_t)f * F_;
    float s1 = 0.f, s2 = 0.f;
#pragma unroll
    for (int i = 0; i < 8; ++i) {
        const int c = lane + i * 32;
        const float v = wrow[c];
        s1 = fmaf(v, a[c], s1);
        s2 = fmaf(v, a[F_ + c], s2);
    }
#pragma unroll
    for (int o = 16; o; o >>= 1) {
        s1 += __shfl_xor_sync(0xffffffffu, s1, o);
        s2 += __shfl_xor_sync(0xffffffffu, s2, o);
    }
    if (lane == 0) { g_wa[f] = s1; g_wa[F_ + f] = s2; }
}

// ---------------------------------------------------------------------------
// Wh1/Wh2 = h @ wa1 / h @ wa2   (fp32, one warp per row)
// ---------------------------------------------------------------------------
__global__ __launch_bounds__(256) void attvec2(const float* __restrict__ h) {
    const int warp = threadIdx.x >> 5, lane = threadIdx.x & 31;
    const int row = blockIdx.x * 8 + warp;
    const float* hr = h + (size_t)row * F_;
    float s1 = 0.f, s2 = 0.f;
#pragma unroll
    for (int i = 0; i < 8; ++i) {
        const int c = lane + i * 32;
        const float v = hr[c];
        s1 = fmaf(v, g_wa[c], s1);
        s2 = fmaf(v, g_wa[F_ + c], s2);
    }
#pragma unroll
    for (int o = 16; o; o >>= 1) {
        s1 += __shfl_xor_sync(0xffffffffu, s1, o);
        s2 += __shfl_xor_sync(0xffffffffu, s2, o);
    }
    if (lane == 0) { g_Wh1[row] = s1; g_Wh2[row] = s2; }
}

// ---------------------------------------------------------------------------
// masked leaky-relu + row softmax -> attention. 8 contiguous elems / thread.
// ---------------------------------------------------------------------------
__global__ __launch_bounds__(256) void softmax_k(const int* __restrict__ adj,
                                                 float* __restrict__ att) {
    __shared__ float red[8];
    const int row = blockIdx.x;
    const int b = row >> 11;
    const int t = threadIdx.x;
    const int4* __restrict__ arow = (const int4*)(adj + (size_t)row * N_) + t * 2;
    const float4* __restrict__ w2 = (const float4*)(g_Wh2 + (size_t)b * N_) + t * 2;
    const float wh1 = g_Wh1[row];

    const int4 a0 = arow[0], a1 = arow[1];
    const float4 x0 = w2[0], x1 = w2[1];
    int am[8] = {a0.x, a0.y, a0.z, a0.w, a1.x, a1.y, a1.z, a1.w};
    float xv[8] = {x0.x, x0.y, x0.z, x0.w, x1.x, x1.y, x1.z, x1.w};

    float v[8];
    float lmax = -3.0e38f;
#pragma unroll
    for (int i = 0; i < 8; ++i) {
        const float x = wh1 + xv[i];
        const float e = x > 0.f ? x : 0.2f * x;          // leaky_relu before mask
        const float s = am[i] > 0 ? e : -9.0e15f;
        v[i] = s;
        lmax = fmaxf(lmax, s);
    }
#pragma unroll
    for (int o = 16; o; o >>= 1) lmax = fmaxf(lmax, __shfl_xor_sync(0xffffffffu, lmax, o));
    if ((t & 31) == 0) red[t >> 5] = lmax;
    __syncthreads();
    float m = red[0];
#pragma unroll
    for (int i = 1; i < 8; ++i) m = fmaxf(m, red[i]);
    __syncthreads();

    float lsum = 0.f;
#pragma unroll
    for (int i = 0; i < 8; ++i) {
        const float p = __expf(v[i] - m);
        v[i] = p;
        lsum += p;
    }
#pragma unroll
    for (int o = 16; o; o >>= 1) lsum += __shfl_xor_sync(0xffffffffu, lsum, o);
    if ((t & 31) == 0) red[t >> 5] = lsum;
    __syncthreads();
    float s = 0.f;
#pragma unroll
    for (int i = 0; i < 8; ++i) s += red[i];
    const float inv = 1.0f / s;

    float4* __restrict__ orow = (float4*)(att + (size_t)row * N_) + t * 2;
    float4 o0 = {v[0] * inv, v[1] * inv, v[2] * inv, v[3] * inv};
    float4 o1 = {v[4] * inv, v[5] * inv, v[6] * inv, v[7] * inv};
    orow[0] = o0;
    orow[1] = o1;
}

// ---------------------------------------------------------------------------
extern "C" void kernel_launch(void* const* d_in, const int* in_sizes, int n_in,
                              void* d_out, int out_size) {
    const float* h   = (const float*)d_in[0];
    const int*   adj = (const int*)  d_in[1];
    const float* W   = (const float*)d_in[2];
    const float* a   = (const float*)d_in[3];
    float* out = (float*)d_out;
    float* att = out + OUT_OFF;

    float* whp = nullptr;
    cudaGetSymbolAddress((void**)&whp, g_Wh);

    cudaFuncSetAttribute((const void*)mma_gemm<F_, false>,
                         cudaFuncAttributeMaxDynamicSharedMemorySize, SMEM_BYTES);
    cudaFuncSetAttribute((const void*)mma_gemm<N_, true>,
                         cudaFuncAttributeMaxDynamicSharedMemorySize, SMEM_BYTES);

    // exact fp32 attention-logit path (independent of tf32 Wh)
    wa_k<<<F_ / 8, 256>>>(W, a);
    attvec2<<<(B_ * N_) / 8, 256>>>(h);
    // Wh = h @ W (tf32 mma)
    mma_gemm<F_, false><<<dim3(F_ / 128, (B_ * N_) / 128, 1), 256, SMEM_BYTES>>>(
        h, F_, 0, W, 0, nullptr, whp, 0);
    // attention
    softmax_k<<<B_ * N_, 256>>>(adj, att);
    // h_prime = att @ Wh ; out = h + elu(h_prime)
    mma_gemm<N_, true><<<dim3(F_ / 128, N_ / 128, B_), 256, SMEM_BYTES>>>(
        att, N_, (long)N_ * N_, whp, (long)N_ * F_, h, out, (long)N_ * F_);
}